// round 2
// baseline (speedup 1.0000x reference)
#include <cuda_runtime.h>

// Problem constants (RGCN): N nodes, E raw edges, R raw relations,
// R_tot = 2R+1 enriched, B bases, EMB hidden, C classes.
constexpr int N_   = 50000;
constexpr int E_   = 500000;
constexpr int R_   = 20;
constexpr int RT_  = 41;     // 2*R_+1
constexpr int B_   = 40;
constexpr int EMB_ = 16;
constexpr int C_   = 16;
constexpr int NE_  = N_ * EMB_;   // 800000

// Scratch (static device globals; no allocation allowed)
__device__ float g_w1[(size_t)RT_ * NE_];   // [41, 50000, 16]  ~131 MB
__device__ float g_h[NE_];                  // node features after layer 1
__device__ int   g_cnt[RT_ * N_];           // per-(r,s) edge counts
__device__ float g_w2[RT_ * EMB_ * C_];     // [41, 16, 16]

// ---------------------------------------------------------------------------
// 0) zero cnt, h, out
__global__ void k_zero(float* __restrict__ out) {
    int i = blockIdx.x * blockDim.x + threadIdx.x;
    if (i < RT_ * N_) g_cnt[i] = 0;
    if (i < NE_) { g_h[i] = 0.0f; out[i] = 0.0f; }
}

// 1) count edges per (r, s) segment (self-loops have count 1 by construction)
__global__ void k_count(const int* __restrict__ src, const int* __restrict__ dst,
                        const int* __restrict__ rel) {
    int i = blockIdx.x * blockDim.x + threadIdx.x;
    if (i >= E_) return;
    int r = rel[i];
    atomicAdd(&g_cnt[r * N_ + src[i]], 1);
    atomicAdd(&g_cnt[(r + R_) * N_ + dst[i]], 1);
}

// 2) w1[r, j] = sum_b comps1[r,b] * bases1[b, j]   (j = n*16+e, 800000 cols)
__global__ void k_w1(const float* __restrict__ comps1,
                     const float* __restrict__ bases1) {
    __shared__ float cs[RT_ * B_];
    for (int t = threadIdx.x; t < RT_ * B_; t += blockDim.x) cs[t] = comps1[t];
    __syncthreads();
    int j = blockIdx.x * blockDim.x + threadIdx.x;
    if (j >= NE_) return;
    float vals[B_];
#pragma unroll
    for (int b = 0; b < B_; b++) vals[b] = bases1[(size_t)b * NE_ + j];
#pragma unroll 1
    for (int r = 0; r < RT_; r++) {
        float acc = 0.0f;
#pragma unroll
        for (int b = 0; b < B_; b++) acc = fmaf(cs[r * B_ + b], vals[b], acc);
        g_w1[(size_t)r * NE_ + j] = acc;
    }
}

// 3) layer-1 edge scatter: h[s,:] += v * w1[r, o, :]
//    4 threads per directed edge, each handles a float4 chunk.
__global__ void k_l1(const int* __restrict__ src, const int* __restrict__ dst,
                     const int* __restrict__ rel) {
    int idx = blockIdx.x * blockDim.x + threadIdx.x;
    if (idx >= 2 * E_ * 4) return;
    int q  = idx & 3;
    int e2 = idx >> 2;
    int s, o, r;
    if (e2 < E_) { s = src[e2]; o = dst[e2]; r = rel[e2]; }
    else         { int e = e2 - E_; s = dst[e]; o = src[e]; r = rel[e] + R_; }
    float v = 1.0f / (float)g_cnt[r * N_ + s];
    const float4 w = *(const float4*)&g_w1[(size_t)r * NE_ + o * EMB_ + q * 4];
    float* hp = &g_h[s * EMB_ + q * 4];
    atomicAdd(hp + 0, v * w.x);
    atomicAdd(hp + 1, v * w.y);
    atomicAdd(hp + 2, v * w.z);
    atomicAdd(hp + 3, v * w.w);
}

// 4) add self-loop contribution (v=1) + bias, relu
__global__ void k_relu(const float* __restrict__ bias1) {
    int j = blockIdx.x * blockDim.x + threadIdx.x;
    if (j >= NE_) return;
    float x = g_h[j] + g_w1[(size_t)(RT_ - 1) * NE_ + j] + bias1[j & 15];
    g_h[j] = x > 0.0f ? x : 0.0f;
}

// 5) w2[r, e, c] = sum_b comps2[r,b] * bases2[b, e, c]
__global__ void k_w2(const float* __restrict__ comps2,
                     const float* __restrict__ bases2) {
    int i = blockIdx.x * blockDim.x + threadIdx.x;
    if (i >= RT_ * EMB_ * C_) return;
    int r = i >> 8, ec = i & 255;
    float acc = 0.0f;
#pragma unroll
    for (int b = 0; b < B_; b++)
        acc = fmaf(comps2[r * B_ + b], bases2[b * 256 + ec], acc);
    g_w2[i] = acc;
}

// 6) layer-2 fused edge pass:
//    out[s, c] += v * sum_e h[o, e] * w2[r, e, c]   (+ bias2 on self-loop edge)
//    Persistent grid-stride; w2 cached in smem once per block.
__global__ void k_l2(const int* __restrict__ src, const int* __restrict__ dst,
                     const int* __restrict__ rel, const float* __restrict__ bias2,
                     float* __restrict__ out) {
    __shared__ float w2s[RT_ * EMB_ * C_];
    for (int t = threadIdx.x; t < RT_ * EMB_ * C_; t += blockDim.x) w2s[t] = g_w2[t];
    __syncthreads();
    const long long total = (long long)(2 * E_ + N_) * C_;
    const long long stride = (long long)gridDim.x * blockDim.x;
    for (long long idx = blockIdx.x * (long long)blockDim.x + threadIdx.x;
         idx < total; idx += stride) {
        int c  = (int)(idx & 15);
        int ed = (int)(idx >> 4);
        int s, o, r;
        float v, extra = 0.0f;
        if (ed < E_) {
            s = src[ed]; o = dst[ed]; r = rel[ed];
            v = 1.0f / (float)g_cnt[r * N_ + s];
        } else if (ed < 2 * E_) {
            int e = ed - E_;
            s = dst[e]; o = src[e]; r = rel[e] + R_;
            v = 1.0f / (float)g_cnt[r * N_ + s];
        } else {
            int n = ed - 2 * E_;
            s = n; o = n; r = RT_ - 1;
            v = 1.0f; extra = bias2[c];
        }
        const float* hp = &g_h[o * EMB_];
        const float* wp = &w2s[r * EMB_ * C_ + c];
        float acc = 0.0f;
#pragma unroll
        for (int e = 0; e < EMB_; e++) acc = fmaf(hp[e], wp[e * C_], acc);
        atomicAdd(&out[s * C_ + c], v * acc + extra);
    }
}

// ---------------------------------------------------------------------------
extern "C" void kernel_launch(void* const* d_in, const int* in_sizes, int n_in,
                              void* d_out, int out_size) {
    const int*   src    = (const int*)d_in[0];
    const int*   dst    = (const int*)d_in[1];
    const int*   rel    = (const int*)d_in[2];
    const float* comps1 = (const float*)d_in[3];
    const float* bases1 = (const float*)d_in[4];
    const float* comps2 = (const float*)d_in[5];
    const float* bases2 = (const float*)d_in[6];
    const float* bias1  = (const float*)d_in[7];
    const float* bias2  = (const float*)d_in[8];
    float* out = (float*)d_out;

    const int T = 256;
    k_zero <<<(RT_ * N_ + T - 1) / T, T>>>(out);
    k_count<<<(E_ + T - 1) / T, T>>>(src, dst, rel);
    k_w1   <<<(NE_ + T - 1) / T, T>>>(comps1, bases1);
    k_l1   <<<(2 * E_ * 4 + T - 1) / T, T>>>(src, dst, rel);
    k_relu <<<(NE_ + T - 1) / T, T>>>(bias1);
    k_w2   <<<(RT_ * EMB_ * C_ + T - 1) / T, T>>>(comps2, bases2);
    k_l2   <<<740, T>>>(src, dst, rel, bias2, out);
}

// round 3
// speedup vs baseline: 1.0791x; 1.0791x over previous
#include <cuda_runtime.h>

// RGCN constants
constexpr int N_   = 50000;
constexpr int E_   = 500000;
constexpr int R_   = 20;
constexpr int RT_  = 41;            // 2R+1
constexpr int B_   = 40;
constexpr int EMB_ = 16;
constexpr int C_   = 16;
constexpr int NE_  = N_ * EMB_;     // 800000
constexpr int RP_  = 21;            // r-pairs (last pair's hi row is a dummy)

// Scratch (static device globals)
__device__ float g_w1[(size_t)(2 * RP_) * NE_];  // 42 rows x 800000 (row 41 dummy)
__device__ float g_h[NE_];
__device__ int   g_cnt[RT_ * N_];
__device__ float g_w2[RT_ * EMB_ * C_];

// ---------------------------------------------------------------------------
__global__ void k_zero(float* __restrict__ out) {
    int i = blockIdx.x * blockDim.x + threadIdx.x;
    if (i < RT_ * N_) g_cnt[i] = 0;
    if (i < NE_) { g_h[i] = 0.0f; out[i] = 0.0f; }
}

__global__ void k_count(const int* __restrict__ src, const int* __restrict__ dst,
                        const int* __restrict__ rel) {
    int i = blockIdx.x * blockDim.x + threadIdx.x;
    if (i >= E_) return;
    int r = rel[i];
    atomicAdd(&g_cnt[r * N_ + src[i]], 1);
    atomicAdd(&g_cnt[(r + R_) * N_ + dst[i]], 1);
}

// ---------------------------------------------------------------------------
// w1[r, j] = sum_b comps1[r,b] * bases1[b, j], computed 2 relations at a time
// with packed f32x2 FMA. smem holds {comps1[2p,b], comps1[2p+1,b]} pairs.
__global__ void k_w1(const float* __restrict__ comps1,
                     const float* __restrict__ bases1) {
    __shared__ unsigned long long cs2[RP_ * B_];
    for (int t = threadIdx.x; t < RP_ * B_; t += blockDim.x) {
        int p = t / B_, b = t % B_;
        float lo = comps1[(2 * p) * B_ + b];
        float hi = (2 * p + 1 < RT_) ? comps1[(2 * p + 1) * B_ + b] : 0.0f;
        unsigned long long packed;
        asm("mov.b64 %0, {%1, %2};" : "=l"(packed)
            : "r"(__float_as_uint(lo)), "r"(__float_as_uint(hi)));
        cs2[t] = packed;
    }
    __syncthreads();
    int j = blockIdx.x * blockDim.x + threadIdx.x;
    if (j >= NE_) return;

    unsigned long long dup[B_];
#pragma unroll
    for (int b = 0; b < B_; b++) {
        unsigned int v = __float_as_uint(bases1[(size_t)b * NE_ + j]);
        asm("mov.b64 %0, {%1, %1};" : "=l"(dup[b]) : "r"(v));
    }
#pragma unroll 1
    for (int p = 0; p < RP_; p++) {
        unsigned long long acc = 0ull;
        const unsigned long long* cp = &cs2[p * B_];
#pragma unroll
        for (int b = 0; b < B_; b++) {
            asm("fma.rn.f32x2 %0, %1, %2, %0;" : "+l"(acc) : "l"(cp[b]), "l"(dup[b]));
        }
        unsigned int lo, hi;
        asm("mov.b64 {%0, %1}, %2;" : "=r"(lo), "=r"(hi) : "l"(acc));
        g_w1[(size_t)(2 * p) * NE_ + j]     = __uint_as_float(lo);
        g_w1[(size_t)(2 * p + 1) * NE_ + j] = __uint_as_float(hi);  // row 41 = dummy
    }
}

// ---------------------------------------------------------------------------
// layer-1 scatter: h[s,:] += v * w1[r, o, :].  4 threads/edge, one float4 each,
// single vectorized RED per thread.
__global__ void k_l1(const int* __restrict__ src, const int* __restrict__ dst,
                     const int* __restrict__ rel) {
    int idx = blockIdx.x * blockDim.x + threadIdx.x;
    if (idx >= 2 * E_ * 4) return;
    int q  = idx & 3;
    int e2 = idx >> 2;
    int s, o, r;
    if (e2 < E_) { s = src[e2]; o = dst[e2]; r = rel[e2]; }
    else         { int e = e2 - E_; s = dst[e]; o = src[e]; r = rel[e] + R_; }
    float v = 1.0f / (float)g_cnt[r * N_ + s];
    const float4 w = *(const float4*)&g_w1[(size_t)r * NE_ + o * EMB_ + q * 4];
    float* hp = &g_h[s * EMB_ + q * 4];
    asm volatile("red.global.add.v4.f32 [%0], {%1, %2, %3, %4};"
                 :: "l"(hp), "f"(v * w.x), "f"(v * w.y), "f"(v * w.z), "f"(v * w.w)
                 : "memory");
}

// self-loop (v=1) + bias + relu
__global__ void k_relu(const float* __restrict__ bias1) {
    int j = blockIdx.x * blockDim.x + threadIdx.x;
    if (j >= NE_) return;
    float x = g_h[j] + g_w1[(size_t)(RT_ - 1) * NE_ + j] + bias1[j & 15];
    g_h[j] = x > 0.0f ? x : 0.0f;
}

__global__ void k_w2(const float* __restrict__ comps2,
                     const float* __restrict__ bases2) {
    int i = blockIdx.x * blockDim.x + threadIdx.x;
    if (i >= RT_ * EMB_ * C_) return;
    int r = i >> 8, ec = i & 255;
    float acc = 0.0f;
#pragma unroll
    for (int b = 0; b < B_; b++)
        acc = fmaf(comps2[r * B_ + b], bases2[b * 256 + ec], acc);
    g_w2[i] = acc;
}

// ---------------------------------------------------------------------------
// layer-2 fused edge pass: out[s,c] += v * sum_e h[o,e] * w2[r,e,c].
// 16 lanes per edge (lane = c); h row loaded coalesced once, broadcast via shfl.
__global__ void k_l2(const int* __restrict__ src, const int* __restrict__ dst,
                     const int* __restrict__ rel, const float* __restrict__ bias2,
                     float* __restrict__ out) {
    __shared__ float w2s[RT_ * EMB_ * C_];
    for (int t = threadIdx.x; t < RT_ * EMB_ * C_; t += blockDim.x) w2s[t] = g_w2[t];
    __syncthreads();

    const int lane = threadIdx.x & 31;
    const int total = (2 * E_ + N_) * C_;                 // 16.8M lane-slots
    const int stride = gridDim.x * blockDim.x;            // multiple of 32
    int tid = blockIdx.x * blockDim.x + threadIdx.x;
    int wbase = tid & ~31;

    for (int s0 = wbase; s0 < total; s0 += stride) {
        int slot = s0 + lane;
        bool active = slot < total;
        int slot_c = active ? slot : (total - 1);
        int c  = slot_c & 15;
        int ed = slot_c >> 4;

        int s, o, r;
        float v, extra = 0.0f;
        if (ed < E_) {
            s = src[ed]; o = dst[ed]; r = rel[ed];
            v = 1.0f / (float)g_cnt[r * N_ + s];
        } else if (ed < 2 * E_) {
            int e = ed - E_;
            s = dst[e]; o = src[e]; r = rel[e] + R_;
            v = 1.0f / (float)g_cnt[r * N_ + s];
        } else {
            int n = ed - 2 * E_;
            s = n; o = n; r = RT_ - 1;
            v = 1.0f; extra = bias2[c];
        }

        float hval = g_h[o * EMB_ + c];       // coalesced 64B per edge
        const float* wp = &w2s[r * EMB_ * C_ + c];
        float acc = 0.0f;
        int base16 = lane & 16;
#pragma unroll
        for (int e = 0; e < EMB_; e++) {
            float he = __shfl_sync(0xffffffffu, hval, base16 | e);
            acc = fmaf(he, wp[e * C_], acc);
        }
        if (active) atomicAdd(&out[s * C_ + c], v * acc + extra);
    }
}

// ---------------------------------------------------------------------------
extern "C" void kernel_launch(void* const* d_in, const int* in_sizes, int n_in,
                              void* d_out, int out_size) {
    const int*   src    = (const int*)d_in[0];
    const int*   dst    = (const int*)d_in[1];
    const int*   rel    = (const int*)d_in[2];
    const float* comps1 = (const float*)d_in[3];
    const float* bases1 = (const float*)d_in[4];
    const float* comps2 = (const float*)d_in[5];
    const float* bases2 = (const float*)d_in[6];
    const float* bias1  = (const float*)d_in[7];
    const float* bias2  = (const float*)d_in[8];
    float* out = (float*)d_out;

    const int T = 256;
    k_zero <<<(RT_ * N_ + T - 1) / T, T>>>(out);
    k_count<<<(E_ + T - 1) / T, T>>>(src, dst, rel);
    k_w1   <<<(NE_ + T - 1) / T, T>>>(comps1, bases1);
    k_l1   <<<(2 * E_ * 4 + T - 1) / T, T>>>(src, dst, rel);
    k_relu <<<(NE_ + T - 1) / T, T>>>(bias1);
    k_w2   <<<(RT_ * EMB_ * C_ + T - 1) / T, T>>>(comps2, bases2);
    k_l2   <<<740, T>>>(src, dst, rel, bias2, out);
}